// round 13
// baseline (speedup 1.0000x reference)
#include <cuda_runtime.h>
#include <cuda_fp16.h>
#include <math.h>

#define B_  8
#define T_  10
#define N_  50
#define IN_ 6
#define H_  256
#define K_  4
#define E_  2450           // N*(N-1)
#define BN  400            // B*N
#define BE  19600          // B*E
#define HH  (H_ * H_)

// ---------------- scratch (device globals) ----------------------------------
__device__ float g_hidden[BN * H_];
__device__ __half g_hidden_h[BN * H_];
__device__ float g_ins[BN * IN_];
__device__ __half g_Uh[6 * BN * H_];        // fp16 Ur/Us
__device__ __half g_M1h[3 * BE * H_];       // fp16 first-layer tanh
__device__ __half g_msgs3h[3 * BE * H_];    // fp16 per-type weighted messages
__device__ __half g_agg_h[BN * H_];

// fp16 weights (converted once per launch)
__device__ __half g_w1h[6 * HH];            // [z][n][k]
__device__ __half g_w2h[3 * HH];            // [type-1][n][k]
__device__ __half g_whh3[3 * HH];           // hr,hi,hh
__device__ __half g_wo1h[HH];
__device__ __half g_wo2h[HH];
__device__ __half g_b1h[3 * H_];

// ---------------- helpers -----------------------------------------------------
__device__ __forceinline__ float tanh_fast(float x) {
    float r; asm("tanh.approx.f32 %0, %1;" : "=f"(r) : "f"(x)); return r;
}
__device__ __forceinline__ float sigmoid_fast(float x) {
    return 0.5f * tanh_fast(0.5f * x) + 0.5f;
}
__device__ __forceinline__ unsigned tanh2(unsigned x) {
    unsigned r; asm("tanh.approx.f16x2 %0, %1;" : "=r"(r) : "r"(x)); return r;
}
__device__ __forceinline__ unsigned h2pack(float lo, float hi) {
    unsigned r;
    asm("cvt.rn.f16x2.f32 %0, %1, %2;" : "=r"(r) : "f"(hi), "f"(lo));
    return r;
}
__device__ __forceinline__ unsigned hadd2u(unsigned a, unsigned b) {
    __half2 r = __hadd2(*reinterpret_cast<__half2*>(&a),
                        *reinterpret_cast<__half2*>(&b));
    return *reinterpret_cast<unsigned*>(&r);
}
__device__ __forceinline__ void mma16(float c[4], const unsigned a[4],
                                      unsigned b0, unsigned b1) {
    asm volatile(
        "mma.sync.aligned.m16n8k16.row.col.f32.f16.f16.f32 "
        "{%0,%1,%2,%3}, {%4,%5,%6,%7}, {%8,%9}, {%0,%1,%2,%3};"
        : "+f"(c[0]), "+f"(c[1]), "+f"(c[2]), "+f"(c[3])
        : "r"(a[0]), "r"(a[1]), "r"(a[2]), "r"(a[3]), "r"(b0), "r"(b1));
}
__device__ __forceinline__ void ldsm4(unsigned& r0, unsigned& r1,
                                      unsigned& r2, unsigned& r3, unsigned addr) {
    asm volatile("ldmatrix.sync.aligned.m8n8.x4.shared.b16 {%0,%1,%2,%3}, [%4];"
                 : "=r"(r0), "=r"(r1), "=r"(r2), "=r"(r3) : "r"(addr));
}
__device__ __forceinline__ unsigned su32(const void* p) {
    return (unsigned)__cvta_generic_to_shared(p);
}
__device__ __forceinline__ void cp16(unsigned dst, const void* src) {
    asm volatile("cp.async.ca.shared.global [%0], [%1], 16;" :: "r"(dst), "l"(src));
}
__device__ __forceinline__ void cp_commit() { asm volatile("cp.async.commit_group;"); }
__device__ __forceinline__ void cp_wait1() { asm volatile("cp.async.wait_group 1;"); }
__device__ __forceinline__ void cp_wait0() { asm volatile("cp.async.wait_group 0;"); }

#define A_LOFF(lane, wm0) ((unsigned)(((wm0) + ((lane) & 15)) * 48 + (((lane) >> 4) << 4)))
#define W_LOFF(lane, wn0) ((unsigned)((((wn0) + (((lane) & 7) | (((lane) >> 4) << 3))) * 48) + ((((lane) >> 3) & 1) << 4)))

// ---------------- one-time fp16 weight conversion ------------------------------
__global__ void cvt_weights(const float* __restrict__ msg_w1,
                            const float* __restrict__ msg_w2,
                            const float* __restrict__ w_hr,
                            const float* __restrict__ w_hi,
                            const float* __restrict__ w_hh,
                            const float* __restrict__ w_o1,
                            const float* __restrict__ w_o2,
                            const float* __restrict__ msg_b1) {
    int idx = blockIdx.x * blockDim.x + threadIdx.x;
    if (idx < 6 * HH) {
        int z = idx / HH, r = idx - z * HH;
        int n = r / H_, k = r - n * H_;
        int it = z >> 1, rs = z & 1;
        g_w1h[idx] = __float2half(
            msg_w1[(size_t)(it + 1) * H_ * 2 * H_ + (size_t)n * 2 * H_ + rs * H_ + k]);
    }
    if (idx < 3 * HH) {
        int i = idx / HH, r = idx - i * HH;
        g_w2h[idx] = __float2half(msg_w2[(size_t)(i + 1) * HH + r]);
    }
    if (idx < HH) {
        g_whh3[idx]          = __float2half(w_hr[idx]);
        g_whh3[HH + idx]     = __float2half(w_hi[idx]);
        g_whh3[2 * HH + idx] = __float2half(w_hh[idx]);
        g_wo1h[idx] = __float2half(w_o1[idx]);
        g_wo2h[idx] = __float2half(w_o2[idx]);
    }
    if (idx < 3 * H_) {
        int z = idx / H_, h = idx - z * H_;
        g_b1h[idx] = __float2half(msg_b1[(size_t)(z + 1) * H_ + h]);
    }
}

// ---------------- fp16 GEMM tile: 64x128, 128 threads (urus/msgs) -------------
__device__ void tc16_tile(
    const __half* __restrict__ A, int lda,
    const __half* __restrict__ W, int ldw,
    __half* __restrict__ Ch, int ldc,
    int M, int row0, int col0)
{
    __shared__ unsigned As[3][64][12];
    __shared__ unsigned Ws[3][128][12];

    const int tid = threadIdx.x;
    const int lane = tid & 31, wid = tid >> 5;
    const int gid = lane >> 2, tig = lane & 3;
    const int wm0 = (wid >> 1) * 32, wn0 = (wid & 1) * 64;
    const int ar = tid >> 1, ap = tid & 1;

    int arow = row0 + ar; if (arow >= M) arow = M - 1;
    const __half* Apt = A + (size_t)arow * lda + ap * 8;
    const __half* Wpt = W + (size_t)(col0 + tid) * ldw;

    const unsigned asA = su32(&As[0][0][0]);
    const unsigned asW = su32(&Ws[0][0][0]);
    const unsigned aoff0 = A_LOFF(lane, wm0);
    const unsigned aoff1 = A_LOFF(lane, wm0 + 16);
    const unsigned woff  = W_LOFF(lane, wn0);

#pragma unroll
    for (int p = 0; p < 2; p++) {
        cp16(su32(&As[p][ar][ap * 4]), Apt + p * 16);
        cp16(su32(&Ws[p][tid][0]), Wpt + p * 16);
        cp16(su32(&Ws[p][tid][4]), Wpt + p * 16 + 8);
        cp_commit();
    }

    float acc[2][8][4];
#pragma unroll
    for (int mi = 0; mi < 2; mi++)
#pragma unroll
        for (int ni = 0; ni < 8; ni++)
#pragma unroll
            for (int j = 0; j < 4; j++) acc[mi][ni][j] = 0.f;

#pragma unroll 1
    for (int c = 0; c < 16; c++) {
        if (c + 1 < 16) cp_wait1(); else cp_wait0();
        __syncthreads();
        int cn = c + 2;
        if (cn < 16) {
            int bf = cn % 3;
            cp16(su32(&As[bf][ar][ap * 4]), Apt + cn * 16);
            cp16(su32(&Ws[bf][tid][0]), Wpt + cn * 16);
            cp16(su32(&Ws[bf][tid][4]), Wpt + cn * 16 + 8);
            cp_commit();
        }
        const int b = c % 3;
        const unsigned abase = asA + (unsigned)b * 3072;
        const unsigned wbase = asW + (unsigned)b * 6144 + woff;
        unsigned a0[4], a1[4];
        ldsm4(a0[0], a0[1], a0[2], a0[3], abase + aoff0);
        ldsm4(a1[0], a1[1], a1[2], a1[3], abase + aoff1);
#pragma unroll
        for (int j = 0; j < 4; j++) {
            unsigned b00, b01, b10, b11;
            ldsm4(b00, b01, b10, b11, wbase + (unsigned)j * 768);
            mma16(acc[0][2 * j],     a0, b00, b01);
            mma16(acc[1][2 * j],     a1, b00, b01);
            mma16(acc[0][2 * j + 1], a0, b10, b11);
            mma16(acc[1][2 * j + 1], a1, b10, b11);
        }
    }

#pragma unroll
    for (int mi = 0; mi < 2; mi++) {
        int r = row0 + wm0 + mi * 16 + gid;
#pragma unroll
        for (int ni = 0; ni < 8; ni++) {
            int cb = col0 + wn0 + ni * 8 + tig * 2;
            if (r < M)     *(__half2*)(Ch + (size_t)r * ldc + cb)       =
                __floats2half2_rn(acc[mi][ni][0], acc[mi][ni][1]);
            if (r + 8 < M) *(__half2*)(Ch + (size_t)(r + 8) * ldc + cb) =
                __floats2half2_rn(acc[mi][ni][2], acc[mi][ni][3]);
        }
    }
}

// ---------------- kernels ------------------------------------------------------

__global__ void init_kernel(const float* __restrict__ inputs) {
    int idx = blockIdx.x * blockDim.x + threadIdx.x;
    if (idx < BN * H_) { g_hidden[idx] = 0.f; g_hidden_h[idx] = __float2half(0.f); }
    if (idx < BN * IN_) {
        int row = idx / IN_, c = idx % IN_;
        int b = row / N_, n = row % N_;
        g_ins[idx] = inputs[(((size_t)b * T_ + 0) * N_ + n) * IN_ + c];
    }
}

__global__ __launch_bounds__(128)
void urus_tc(int dummy) {
    int z = blockIdx.z;
    tc16_tile(g_hidden_h, H_, g_w1h + (size_t)z * HH, H_,
              g_Uh + (size_t)z * BN * H_, H_,
              BN, blockIdx.x * 64, blockIdx.y * 128);
}

// ---- M1h: tanh(Ur[recv]+Us[send]+b1) fp16x2 ----------------------------------
__global__ __launch_bounds__(256)
void m1h_kernel() {
    const int tid = threadIdx.x;
    const int warp = tid >> 5, lane = tid & 31;
    const int row = blockIdx.x * 8 + warp;
    const int z = blockIdx.y;
    int b = row / E_;
    int e = row - b * E_;
    int send = e / 49, rr2 = e - send * 49;
    int recv = rr2 + (rr2 >= send);

    const __half* Ur = g_Uh + ((size_t)(2 * z) * BN + b * N_ + recv) * H_ + lane * 8;
    const __half* Us = g_Uh + ((size_t)(2 * z + 1) * BN + b * N_ + send) * H_ + lane * 8;
    const __half* B1 = g_b1h + (size_t)z * H_ + lane * 8;

    uint4 u = *(const uint4*)Ur;
    uint4 s = *(const uint4*)Us;
    uint4 bb = *(const uint4*)B1;
    uint4 o;
    o.x = tanh2(hadd2u(hadd2u(u.x, s.x), bb.x));
    o.y = tanh2(hadd2u(hadd2u(u.y, s.y), bb.y));
    o.z = tanh2(hadd2u(hadd2u(u.z, s.z), bb.z));
    o.w = tanh2(hadd2u(hadd2u(u.w, s.w), bb.w));
    *(uint4*)(g_M1h + ((size_t)z * BE + row) * H_ + lane * 8) = o;
}

// ======== edge-message GEMM (unchanged r12 structure) ==========================
__global__ __launch_bounds__(128, 4)
void msgs_f16_kernel(const float* __restrict__ msg_b2,
                     const float* __restrict__ edges, int t)
{
    __shared__ unsigned As[3][64][12];
    __shared__ unsigned Ws[3][128][12];
    __shared__ float relw[64];
    __shared__ float b2s[128];

    const int tid = threadIdx.x;
    const int lane = tid & 31, wid = tid >> 5;
    const int gid = lane >> 2, tig = lane & 3;
    const int wm0 = (wid >> 1) * 32, wn0 = (wid & 1) * 64;
    const int row0 = blockIdx.x * 64, col0 = blockIdx.y * 128;
    const int z = blockIdx.z, type = z + 1;

    if (tid < 64) {
        int r = row0 + tid;
        int valid = (r < BE);
        if (!valid) r = BE - 1;
        int b = r / E_;
        int e = r - b * E_;
        relw[tid] = valid
            ? edges[(((size_t)b * T_ + t) * E_ + e) * K_ + type] * (1.f / 3.f)
            : 0.f;
    }
    b2s[tid] = msg_b2[(size_t)type * H_ + col0 + tid];

    const int ar = tid >> 1, ap = tid & 1;
    int arow = row0 + ar; if (arow >= BE) arow = BE - 1;
    const __half* Apt = g_M1h + ((size_t)z * BE + arow) * H_ + ap * 8;
    const __half* Wpt = g_w2h + ((size_t)z * H_ + (col0 + tid)) * H_;

    const unsigned asA = su32(&As[0][0][0]);
    const unsigned asW = su32(&Ws[0][0][0]);
    const unsigned aoff0 = A_LOFF(lane, wm0);
    const unsigned aoff1 = A_LOFF(lane, wm0 + 16);
    const unsigned woff  = W_LOFF(lane, wn0);

#pragma unroll
    for (int p = 0; p < 2; p++) {
        cp16(su32(&As[p][ar][ap * 4]), Apt + p * 16);
        cp16(su32(&Ws[p][tid][0]), Wpt + p * 16);
        cp16(su32(&Ws[p][tid][4]), Wpt + p * 16 + 8);
        cp_commit();
    }

    float acc[2][8][4];
#pragma unroll
    for (int mi = 0; mi < 2; mi++)
#pragma unroll
        for (int ni = 0; ni < 8; ni++)
#pragma unroll
            for (int j = 0; j < 4; j++) acc[mi][ni][j] = 0.f;

#pragma unroll 1
    for (int c = 0; c < 16; c++) {
        if (c + 1 < 16) cp_wait1(); else cp_wait0();
        __syncthreads();
        int cn = c + 2;
        if (cn < 16) {
            int bf = cn % 3;
            cp16(su32(&As[bf][ar][ap * 4]), Apt + cn * 16);
            cp16(su32(&Ws[bf][tid][0]), Wpt + cn * 16);
            cp16(su32(&Ws[bf][tid][4]), Wpt + cn * 16 + 8);
            cp_commit();
        }
        const int b = c % 3;
        const unsigned abase = asA + (unsigned)b * 3072;
        const unsigned wbase = asW + (unsigned)b * 6144 + woff;
        unsigned a0[4], a1[4];
        ldsm4(a0[0], a0[1], a0[2], a0[3], abase + aoff0);
        ldsm4(a1[0], a1[1], a1[2], a1[3], abase + aoff1);
#pragma unroll
        for (int j = 0; j < 4; j++) {
            unsigned b00, b01, b10, b11;
            ldsm4(b00, b01, b10, b11, wbase + (unsigned)j * 768);
            mma16(acc[0][2 * j],     a0, b00, b01);
            mma16(acc[1][2 * j],     a1, b00, b01);
            mma16(acc[0][2 * j + 1], a0, b10, b11);
            mma16(acc[1][2 * j + 1], a1, b10, b11);
        }
    }

    __half* Cz = g_msgs3h + (size_t)z * BE * H_;
#pragma unroll
    for (int mi = 0; mi < 2; mi++) {
        int r = row0 + wm0 + mi * 16 + gid;
        __half2 rl0 = __float2half2_rn(relw[wm0 + mi * 16 + gid]);
        __half2 rl1 = __float2half2_rn(relw[wm0 + mi * 16 + gid + 8]);
#pragma unroll
        for (int ni = 0; ni < 8; ni++) {
            int cb = col0 + wn0 + ni * 8 + tig * 2;
            float bb0 = b2s[wn0 + ni * 8 + tig * 2];
            float bb1 = b2s[wn0 + ni * 8 + tig * 2 + 1];
            if (r < BE) {
                unsigned tr = tanh2(h2pack(acc[mi][ni][0] + bb0, acc[mi][ni][1] + bb1));
                *(__half2*)(Cz + (size_t)r * H_ + cb) =
                    __hmul2(*reinterpret_cast<__half2*>(&tr), rl0);
            }
            if (r + 8 < BE) {
                unsigned tr = tanh2(h2pack(acc[mi][ni][2] + bb0, acc[mi][ni][3] + bb1));
                *(__half2*)(Cz + (size_t)(r + 8) * H_ + cb) =
                    __hmul2(*reinterpret_cast<__half2*>(&tr), rl1);
            }
        }
    }
}

// agg: sum 3 fp16 type-buffers over 49 senders -> fp16
__global__ __launch_bounds__(256)
void agg_kernel() {
    __shared__ float part[3][256];
    const int tid = threadIdx.x;
    const int sg = tid >> 6;
    const int hq = tid & 63;
    const int row = blockIdx.x;
    const int b = row / N_, r = row - b * N_;
    float4 s = make_float4(0.f, 0.f, 0.f, 0.f);
#pragma unroll
    for (int z = 0; z < 3; z++) {
        const __half* base = g_msgs3h + ((size_t)z * BE + (size_t)b * E_) * H_ + hq * 4;
        for (int send = sg; send < N_; send += 4) {
            if (send == r) continue;
            int e = send * 49 + r - (r > send);
            uint2 raw = *(const uint2*)(base + (size_t)e * H_);
            float2 f01 = __half22float2(*reinterpret_cast<__half2*>(&raw.x));
            float2 f23 = __half22float2(*reinterpret_cast<__half2*>(&raw.y));
            s.x += f01.x; s.y += f01.y; s.z += f23.x; s.w += f23.y;
        }
    }
    if (sg > 0) *(float4*)&part[sg - 1][hq * 4] = s;
    __syncthreads();
    if (sg == 0) {
        const float4 p0 = *(const float4*)&part[0][hq * 4];
        const float4 p1 = *(const float4*)&part[1][hq * 4];
        const float4 p2 = *(const float4*)&part[2][hq * 4];
        const float inv = 1.f / 49.f;
        float4 o;
        o.x = (s.x + p0.x + p1.x + p2.x) * inv;
        o.y = (s.y + p0.y + p1.y + p2.y) * inv;
        o.z = (s.z + p0.z + p1.z + p2.z) * inv;
        o.w = (s.w + p0.w + p1.w + p2.w) * inv;
        *(__half2*)(g_agg_h + (size_t)row * H_ + hq * 4)     = __floats2half2_rn(o.x, o.y);
        *(__half2*)(g_agg_h + (size_t)row * H_ + hq * 4 + 2) = __floats2half2_rn(o.z, o.w);
    }
}

// ================= fused node kernel: gru(3) + gruew + p1 + p2 + f3 ============
// 7 blocks x 256 threads. Block handles 64 rows. Smem A/R/I buffers [64][132]w.
#define AROW_W 132
#define AROW_B 528
#define AB_OFF 0
#define RB_OFF 33792
#define IB_OFF 67584
#define WS_OFF 101376
#define NODE_SMEM 138240

// K=256, N=256 GEMM: A from smem (ldmatrix layout, row stride 528B), W global.
__device__ __forceinline__ void fgemm256(
    unsigned abase, unsigned wsbase, const __half* __restrict__ Wg,
    float acc[2][8][4])
{
    const int tid = threadIdx.x, lane = tid & 31, wid = tid >> 5;
    const int wm0 = (wid >> 2) * 32, wn0 = (wid & 3) * 64;
    const __half* Wpt = Wg + (size_t)tid * H_;
    const unsigned wsrow = wsbase + tid * 48;
#pragma unroll
    for (int p = 0; p < 2; p++) {
        cp16(wsrow + p * 12288, Wpt + p * 16);
        cp16(wsrow + p * 12288 + 16, Wpt + p * 16 + 8);
        cp_commit();
    }
#pragma unroll
    for (int mi = 0; mi < 2; mi++)
#pragma unroll
        for (int ni = 0; ni < 8; ni++)
#pragma unroll
            for (int j = 0; j < 4; j++) acc[mi][ni][j] = 0.f;

    const unsigned aoff0 = abase + (wm0 + (lane & 15)) * AROW_B + ((lane >> 4) << 4);
    const unsigned aoff1 = aoff0 + 16 * AROW_B;
    const unsigned woff = wsbase
        + (wn0 + ((lane & 7) | ((lane >> 4) << 3))) * 48 + (((lane >> 3) & 1) << 4);

#pragma unroll 1
    for (int c = 0; c < 16; c++) {
        if (c + 1 < 16) cp_wait1(); else cp_wait0();
        __syncthreads();
        int cn = c + 2;
        if (cn < 16) {
            int bf = cn % 3;
            cp16(wsrow + bf * 12288, Wpt + cn * 16);
            cp16(wsrow + bf * 12288 + 16, Wpt + cn * 16 + 8);
            cp_commit();
        }
        const int b = c % 3;
        unsigned a0[4], a1[4];
        ldsm4(a0[0], a0[1], a0[2], a0[3], aoff0 + c * 32);
        ldsm4(a1[0], a1[1], a1[2], a1[3], aoff1 + c * 32);
        const unsigned wb = woff + (unsigned)b * 12288;
#pragma unroll
        for (int j = 0; j < 4; j++) {
            unsigned b00, b01, b10, b11;
            ldsm4(b00, b01, b10, b11, wb + (unsigned)j * 768);
            mma16(acc[0][2 * j],     a0, b00, b01);
            mma16(acc[1][2 * j],     a1, b00, b01);
            mma16(acc[0][2 * j + 1], a0, b10, b11);
            mma16(acc[1][2 * j + 1], a1, b10, b11);
        }
    }
}

// store acc fragment to smem fp16 buffer [64][132]w, optional bias+relu
__device__ __forceinline__ void ep_store(float acc[2][8][4], unsigned* buf,
                                         const float* __restrict__ bias, int relu)
{
    const int tid = threadIdx.x, lane = tid & 31, wid = tid >> 5;
    const int gid = lane >> 2, tig = lane & 3;
    const int wm0 = (wid >> 2) * 32, wn0 = (wid & 3) * 64;
#pragma unroll
    for (int mi = 0; mi < 2; mi++) {
        int r = wm0 + mi * 16 + gid;
#pragma unroll
        for (int ni = 0; ni < 8; ni++) {
            int c0 = wn0 + ni * 8 + tig * 2;
            float b0 = 0.f, b1 = 0.f;
            if (bias) { b0 = bias[c0]; b1 = bias[c0 + 1]; }
            float v0 = acc[mi][ni][0] + b0, v1 = acc[mi][ni][1] + b1;
            float v2 = acc[mi][ni][2] + b0, v3 = acc[mi][ni][3] + b1;
            if (relu) {
                v0 = fmaxf(v0, 0.f); v1 = fmaxf(v1, 0.f);
                v2 = fmaxf(v2, 0.f); v3 = fmaxf(v3, 0.f);
            }
            buf[r * AROW_W + (c0 >> 1)]       = h2pack(v0, v1);
            buf[(r + 8) * AROW_W + (c0 >> 1)] = h2pack(v2, v3);
        }
    }
}

__global__ __launch_bounds__(256)
void node_fused(const float* __restrict__ w_ir, const float* __restrict__ b_ir,
                const float* __restrict__ w_ii, const float* __restrict__ b_ii,
                const float* __restrict__ w_in, const float* __restrict__ b_in,
                const float* __restrict__ b_o1, const float* __restrict__ b_o2,
                const float* __restrict__ w_o3, const float* __restrict__ b_o3,
                float* __restrict__ out, int t)
{
    extern __shared__ char smem[];
    unsigned* Abuf = (unsigned*)(smem + AB_OFF);
    unsigned* Rbuf = (unsigned*)(smem + RB_OFF);
    unsigned* Ibuf = (unsigned*)(smem + IB_OFF);
    const unsigned sbase = su32(smem);
    const unsigned abase = sbase + AB_OFF;
    const unsigned rbase = sbase + RB_OFF;
    const unsigned ibase = sbase + IB_OFF;
    const unsigned wsbase = sbase + WS_OFF;

    const int tid = threadIdx.x, lane = tid & 31, wid = tid >> 5;
    const int gid = lane >> 2, tig = lane & 3;
    const int wm0 = (wid >> 2) * 32, wn0 = (wid & 3) * 64;
    const int row0 = blockIdx.x * 64;

    // ---- load agg rows into Abuf ----
    {
        int r = tid >> 2, q = tid & 3;
        int grow = row0 + r; if (grow >= BN) grow = BN - 1;
        const __half* src = g_agg_h + (size_t)grow * H_ + q * 64;
        unsigned dst = abase + r * AROW_B + q * 128;
#pragma unroll
        for (int i = 0; i < 8; i++) cp16(dst + i * 16, src + i * 8);
        cp_commit(); cp_wait0();
        __syncthreads();
    }

    float acc[2][8][4];

    // ---- GEMM r -> Rbuf, GEMM i -> Ibuf, GEMM h -> acc ----
    fgemm256(abase, wsbase, g_whh3, acc);
    ep_store(acc, Rbuf, nullptr, 0);
    __syncthreads();
    fgemm256(abase, wsbase, g_whh3 + HH, acc);
    ep_store(acc, Ibuf, nullptr, 0);
    __syncthreads();
    fgemm256(abase, wsbase, g_whh3 + 2 * HH, acc);
    __syncthreads();

    // ---- GRU elementwise: acc = ah; R/I from smem; hidden -> Abuf + global ----
    {
        float insv[4][6];
#pragma unroll
        for (int k = 0; k < 4; k++) {
            int grow = row0 + wm0 + k * 8 + gid;
#pragma unroll
            for (int f = 0; f < 6; f++)
                insv[k][f] = (grow < BN) ? g_ins[grow * IN_ + f] : 0.f;
        }
#pragma unroll
        for (int ni = 0; ni < 8; ni++) {
            int c0 = wn0 + ni * 8 + tig * 2;
            float wr0[6], wr1[6], wi0[6], wi1[6], wn0v[6], wn1v[6];
#pragma unroll
            for (int f = 0; f < 6; f++) {
                wr0[f] = w_ir[c0 * 6 + f];       wr1[f] = w_ir[(c0 + 1) * 6 + f];
                wi0[f] = w_ii[c0 * 6 + f];       wi1[f] = w_ii[(c0 + 1) * 6 + f];
                wn0v[f] = w_in[c0 * 6 + f];      wn1v[f] = w_in[(c0 + 1) * 6 + f];
            }
            float br0 = b_ir[c0], br1 = b_ir[c0 + 1];
            float bi0 = b_ii[c0], bi1 = b_ii[c0 + 1];
            float bn0 = b_in[c0], bn1 = b_in[c0 + 1];
#pragma unroll
            for (int mi = 0; mi < 2; mi++) {
#pragma unroll
                for (int pr = 0; pr < 2; pr++) {
                    int rl = wm0 + mi * 16 + pr * 8 + gid;
                    int k = mi * 2 + pr;
                    float xr0 = br0, xr1 = br1, xi0 = bi0, xi1 = bi1, xn0 = bn0, xn1 = bn1;
#pragma unroll
                    for (int f = 0; f < 6; f++) {
                        float iv = insv[k][f];
                        xr0 += iv * wr0[f];  xr1 += iv * wr1[f];
                        xi0 += iv * wi0[f];  xi1 += iv * wi1[f];
                        xn0 += iv * wn0v[f]; xn1 += iv * wn1v[f];
                    }
                    unsigned rw = Rbuf[rl * AROW_W + (c0 >> 1)];
                    unsigned iw = Ibuf[rl * AROW_W + (c0 >> 1)];
                    float2 aR = __half22float2(*reinterpret_cast<__half2*>(&rw));
                    float2 aI = __half22float2(*reinterpret_cast<__half2*>(&iw));
                    float ah0 = acc[mi][ni][pr * 2], ah1 = acc[mi][ni][pr * 2 + 1];
                    float r0 = sigmoid_fast(xr0 + aR.x);
                    float r1 = sigmoid_fast(xr1 + aR.y);
                    float ig0 = sigmoid_fast(xi0 + aI.x);
                    float ig1 = sigmoid_fast(xi1 + aI.y);
                    float nn0 = tanh_fast(xn0 + r0 * ah0);
                    float nn1 = tanh_fast(xn1 + r1 * ah1);
                    int grow = row0 + rl;
                    float h0, h1;
                    if (grow < BN) {
                        float old0 = g_hidden[grow * H_ + c0];
                        float old1 = g_hidden[grow * H_ + c0 + 1];
                        h0 = (1.f - ig0) * nn0 + ig0 * old0;
                        h1 = (1.f - ig1) * nn1 + ig1 * old1;
                        g_hidden[grow * H_ + c0] = h0;
                        g_hidden[grow * H_ + c0 + 1] = h1;
                        *(__half2*)(g_hidden_h + (size_t)grow * H_ + c0) =
                            __floats2half2_rn(h0, h1);
                    } else { h0 = 0.f; h1 = 0.f; }
                    Abuf[rl * AROW_W + (c0 >> 1)] = h2pack(h0, h1);
                }
            }
        }
    }
    __syncthreads();

    // ---- p1 = relu(hidden @ w_o1^T + b_o1) -> Rbuf ----
    fgemm256(abase, wsbase, g_wo1h, acc);
    ep_store(acc, Rbuf, b_o1, 1);
    __syncthreads();

    // ---- p2 = relu(p1 @ w_o2^T + b_o2) -> Ibuf ----
    fgemm256(rbase, wsbase, g_wo2h, acc);
    ep_store(acc, Ibuf, b_o2, 1);
    __syncthreads();

    // ---- f3: out = ins + p2 @ w_o3^T + b_o3 ----
    {
        int rl = tid >> 2, q = tid & 3;
        int grow = row0 + rl;
        float a6[6] = {0.f, 0.f, 0.f, 0.f, 0.f, 0.f};
        if (grow < BN) {
            const unsigned* src = Ibuf + rl * AROW_W + q * 32;
            int cb = q * 64;
#pragma unroll 8
            for (int w = 0; w < 32; w++) {
                float2 f = __half22float2(*reinterpret_cast<const __half2*>(&src[w]));
                int c = cb + 2 * w;
#pragma unroll
                for (int k = 0; k < 6; k++)
                    a6[k] += f.x * w_o3[k * H_ + c] + f.y * w_o3[k * H_ + c + 1];
            }
        }
#pragma unroll
        for (int k = 0; k < 6; k++) {
            a6[k] += __shfl_down_sync(0xffffffffu, a6[k], 2);
            a6[k] += __shfl_down_sync(0xffffffffu, a6[k], 1);
        }
        if (q == 0 && grow < BN) {
            int b = grow / N_, n = grow - b * N_;
#pragma unroll
            for (int k = 0; k < 6; k++) {
                float v = g_ins[grow * IN_ + k] + b_o3[k] + a6[k];
                out[(((size_t)b * T_ + t) * N_ + n) * IN_ + k] = v;
                g_ins[grow * IN_ + k] = v;
            }
        }
    }
}

// ---------------- launch ---------------------------------------------------------
extern "C" void kernel_launch(void* const* d_in, const int* in_sizes, int n_in,
                              void* d_out, int out_size) {
    const float* inputs = (const float*)d_in[0];
    const float* edges  = (const float*)d_in[1];
    const float* msg_w1 = (const float*)d_in[2];
    const float* msg_b1 = (const float*)d_in[3];
    const float* msg_w2 = (const float*)d_in[4];
    const float* msg_b2 = (const float*)d_in[5];
    const float* w_hr = (const float*)d_in[6];
    const float* w_hi = (const float*)d_in[7];
    const float* w_hh = (const float*)d_in[8];
    const float* w_ir = (const float*)d_in[9];
    const float* b_ir = (const float*)d_in[10];
    const float* w_ii = (const float*)d_in[11];
    const float* b_ii = (const float*)d_in[12];
    const float* w_in_ = (const float*)d_in[13];
    const float* b_in_ = (const float*)d_in[14];
    const float* w_o1 = (const float*)d_in[15];
    const float* b_o1 = (const float*)d_in[16];
    const float* w_o2 = (const float*)d_in[17];
    const float* b_o2 = (const float*)d_in[18];
    const float* w_o3 = (const float*)d_in[19];
    const float* b_o3 = (const float*)d_in[20];
    float* out = (float*)d_out;

    cudaFuncSetAttribute(node_fused,
                         cudaFuncAttributeMaxDynamicSharedMemorySize, NODE_SMEM);

    cvt_weights<<<(6 * HH + 255) / 256, 256>>>(msg_w1, msg_w2, w_hr, w_hi, w_hh,
                                               w_o1, w_o2, msg_b1);
    init_kernel<<<(BN * H_ + 255) / 256, 256>>>(inputs);

    const int rowt = (BE + 63) / 64;  // 307
    for (int t = 0; t < T_; t++) {
        urus_tc<<<dim3(7, 2, 6), 128>>>(0);
        m1h_kernel<<<dim3(BE / 8, 3), 256>>>();
        msgs_f16_kernel<<<dim3(rowt, 2, 3), 128>>>(msg_b2, edges, t);
        agg_kernel<<<BN, 256>>>();
        node_fused<<<7, 256, NODE_SMEM>>>(w_ir, b_ir, w_ii, b_ii, w_in_, b_in_,
                                          b_o1, b_o2, w_o3, b_o3, out, t);
    }
}

// round 14
// speedup vs baseline: 1.5359x; 1.5359x over previous
#include <cuda_runtime.h>
#include <cuda_fp16.h>
#include <math.h>

#define B_  8
#define T_  10
#define N_  50
#define IN_ 6
#define H_  256
#define K_  4
#define E_  2450           // N*(N-1)
#define BN  400            // B*N
#define BE  19600          // B*E
#define HH  (H_ * H_)

// ---------------- scratch (device globals) ----------------------------------
__device__ float g_hidden[BN * H_];
__device__ __half g_hidden_h[BN * H_];
__device__ float g_ins[BN * IN_];
__device__ __half g_Uh[6 * BN * H_];        // fp16 Ur/Us
__device__ __half g_M1h[3 * BE * H_];       // fp16 first-layer tanh
__device__ __half g_msgs3h[3 * BE * H_];    // fp16 per-type weighted messages
__device__ __half g_agg_h[BN * H_];
__device__ float g_gru[3 * BN * H_];
__device__ __half g_p1h[BN * H_];
__device__ float g_p2[BN * H_];

// fp16 weights (converted once per launch)
__device__ __half g_w1h[6 * HH];            // [z][n][k]
__device__ __half g_w2h[3 * HH];            // [type-1][n][k]
__device__ __half g_whh3[3 * HH];           // hr,hi,hh
__device__ __half g_wo1h[HH];
__device__ __half g_wo2h[HH];
__device__ __half g_b1h[3 * H_];

// ---------------- helpers -----------------------------------------------------
__device__ __forceinline__ float tanh_fast(float x) {
    float r; asm("tanh.approx.f32 %0, %1;" : "=f"(r) : "f"(x)); return r;
}
__device__ __forceinline__ float sigmoid_fast(float x) {
    return 0.5f * tanh_fast(0.5f * x) + 0.5f;
}
__device__ __forceinline__ unsigned tanh2(unsigned x) {
    unsigned r; asm("tanh.approx.f16x2 %0, %1;" : "=r"(r) : "r"(x)); return r;
}
__device__ __forceinline__ unsigned h2pack(float lo, float hi) {
    unsigned r;
    asm("cvt.rn.f16x2.f32 %0, %1, %2;" : "=r"(r) : "f"(hi), "f"(lo));
    return r;
}
__device__ __forceinline__ unsigned hadd2u(unsigned a, unsigned b) {
    __half2 r = __hadd2(*reinterpret_cast<__half2*>(&a),
                        *reinterpret_cast<__half2*>(&b));
    return *reinterpret_cast<unsigned*>(&r);
}
__device__ __forceinline__ void mma16(float c[4], const unsigned a[4],
                                      unsigned b0, unsigned b1) {
    asm volatile(
        "mma.sync.aligned.m16n8k16.row.col.f32.f16.f16.f32 "
        "{%0,%1,%2,%3}, {%4,%5,%6,%7}, {%8,%9}, {%0,%1,%2,%3};"
        : "+f"(c[0]), "+f"(c[1]), "+f"(c[2]), "+f"(c[3])
        : "r"(a[0]), "r"(a[1]), "r"(a[2]), "r"(a[3]), "r"(b0), "r"(b1));
}
__device__ __forceinline__ void ldsm4(unsigned& r0, unsigned& r1,
                                      unsigned& r2, unsigned& r3, unsigned addr) {
    asm volatile("ldmatrix.sync.aligned.m8n8.x4.shared.b16 {%0,%1,%2,%3}, [%4];"
                 : "=r"(r0), "=r"(r1), "=r"(r2), "=r"(r3) : "r"(addr));
}
__device__ __forceinline__ unsigned su32(const void* p) {
    return (unsigned)__cvta_generic_to_shared(p);
}
__device__ __forceinline__ void cp16(unsigned dst, const void* src) {
    asm volatile("cp.async.ca.shared.global [%0], [%1], 16;" :: "r"(dst), "l"(src));
}
__device__ __forceinline__ void cp_commit() { asm volatile("cp.async.commit_group;"); }
__device__ __forceinline__ void cp_wait1() { asm volatile("cp.async.wait_group 1;"); }
__device__ __forceinline__ void cp_wait0() { asm volatile("cp.async.wait_group 0;"); }

#define A_LOFF(lane, wm0) ((unsigned)(((wm0) + ((lane) & 15)) * 48 + (((lane) >> 4) << 4)))
#define W_LOFF(lane, wn0) ((unsigned)((((wn0) + (((lane) & 7) | (((lane) >> 4) << 3))) * 48) + ((((lane) >> 3) & 1) << 4)))

// ---------------- one-time fp16 weight conversion ------------------------------
__global__ void cvt_weights(const float* __restrict__ msg_w1,
                            const float* __restrict__ msg_w2,
                            const float* __restrict__ w_hr,
                            const float* __restrict__ w_hi,
                            const float* __restrict__ w_hh,
                            const float* __restrict__ w_o1,
                            const float* __restrict__ w_o2,
                            const float* __restrict__ msg_b1) {
    int idx = blockIdx.x * blockDim.x + threadIdx.x;
    if (idx < 6 * HH) {
        int z = idx / HH, r = idx - z * HH;
        int n = r / H_, k = r - n * H_;
        int it = z >> 1, rs = z & 1;
        g_w1h[idx] = __float2half(
            msg_w1[(size_t)(it + 1) * H_ * 2 * H_ + (size_t)n * 2 * H_ + rs * H_ + k]);
    }
    if (idx < 3 * HH) {
        int i = idx / HH, r = idx - i * HH;
        g_w2h[idx] = __float2half(msg_w2[(size_t)(i + 1) * HH + r]);
    }
    if (idx < HH) {
        g_whh3[idx]          = __float2half(w_hr[idx]);
        g_whh3[HH + idx]     = __float2half(w_hi[idx]);
        g_whh3[2 * HH + idx] = __float2half(w_hh[idx]);
        g_wo1h[idx] = __float2half(w_o1[idx]);
        g_wo2h[idx] = __float2half(w_o2[idx]);
    }
    if (idx < 3 * H_) {
        int z = idx / H_, h = idx - z * H_;
        g_b1h[idx] = __float2half(msg_b1[(size_t)(z + 1) * H_ + h]);
    }
}

// ---------------- fp16 GEMM tile: 64x128, 128 threads --------------------------
__device__ void tc16_tile(
    const __half* __restrict__ A, int lda,
    const __half* __restrict__ W, int ldw,
    const float* __restrict__ bias,
    float* __restrict__ Cf, __half* __restrict__ Ch, int ldc,
    int M, int row0, int col0, int act)
{
    __shared__ unsigned As[3][64][12];
    __shared__ unsigned Ws[3][128][12];

    const int tid = threadIdx.x;
    const int lane = tid & 31, wid = tid >> 5;
    const int gid = lane >> 2, tig = lane & 3;
    const int wm0 = (wid >> 1) * 32, wn0 = (wid & 1) * 64;
    const int ar = tid >> 1, ap = tid & 1;

    int arow = row0 + ar; if (arow >= M) arow = M - 1;
    const __half* Apt = A + (size_t)arow * lda + ap * 8;
    const __half* Wpt = W + (size_t)(col0 + tid) * ldw;

    const unsigned asA = su32(&As[0][0][0]);
    const unsigned asW = su32(&Ws[0][0][0]);
    const unsigned aoff0 = A_LOFF(lane, wm0);
    const unsigned aoff1 = A_LOFF(lane, wm0 + 16);
    const unsigned woff  = W_LOFF(lane, wn0);

#pragma unroll
    for (int p = 0; p < 2; p++) {
        cp16(su32(&As[p][ar][ap * 4]), Apt + p * 16);
        cp16(su32(&Ws[p][tid][0]), Wpt + p * 16);
        cp16(su32(&Ws[p][tid][4]), Wpt + p * 16 + 8);
        cp_commit();
    }

    float acc[2][8][4];
#pragma unroll
    for (int mi = 0; mi < 2; mi++)
#pragma unroll
        for (int ni = 0; ni < 8; ni++)
#pragma unroll
            for (int j = 0; j < 4; j++) acc[mi][ni][j] = 0.f;

#pragma unroll 1
    for (int c = 0; c < 16; c++) {
        if (c + 1 < 16) cp_wait1(); else cp_wait0();
        __syncthreads();
        int cn = c + 2;
        if (cn < 16) {
            int bf = cn % 3;
            cp16(su32(&As[bf][ar][ap * 4]), Apt + cn * 16);
            cp16(su32(&Ws[bf][tid][0]), Wpt + cn * 16);
            cp16(su32(&Ws[bf][tid][4]), Wpt + cn * 16 + 8);
            cp_commit();
        }
        const int b = c % 3;
        const unsigned abase = asA + (unsigned)b * 3072;
        const unsigned wbase = asW + (unsigned)b * 6144 + woff;
        unsigned a0[4], a1[4];
        ldsm4(a0[0], a0[1], a0[2], a0[3], abase + aoff0);
        ldsm4(a1[0], a1[1], a1[2], a1[3], abase + aoff1);
#pragma unroll
        for (int j = 0; j < 4; j++) {
            unsigned b00, b01, b10, b11;
            ldsm4(b00, b01, b10, b11, wbase + (unsigned)j * 768);
            mma16(acc[0][2 * j],     a0, b00, b01);
            mma16(acc[1][2 * j],     a1, b00, b01);
            mma16(acc[0][2 * j + 1], a0, b10, b11);
            mma16(acc[1][2 * j + 1], a1, b10, b11);
        }
    }

#pragma unroll
    for (int mi = 0; mi < 2; mi++) {
        int r = row0 + wm0 + mi * 16 + gid;
#pragma unroll
        for (int ni = 0; ni < 8; ni++) {
            int cb = col0 + wn0 + ni * 8 + tig * 2;
            float b0 = 0.f, b1 = 0.f;
            if (bias) { b0 = bias[cb]; b1 = bias[cb + 1]; }
            float v0 = acc[mi][ni][0] + b0, v1 = acc[mi][ni][1] + b1;
            float v2 = acc[mi][ni][2] + b0, v3 = acc[mi][ni][3] + b1;
            if (act == 1) {
                v0 = fmaxf(v0, 0.f); v1 = fmaxf(v1, 0.f);
                v2 = fmaxf(v2, 0.f); v3 = fmaxf(v3, 0.f);
            }
            if (Cf) {
                if (r < M)     *(float2*)(Cf + (size_t)r * ldc + cb)       = make_float2(v0, v1);
                if (r + 8 < M) *(float2*)(Cf + (size_t)(r + 8) * ldc + cb) = make_float2(v2, v3);
            } else {
                if (r < M)     *(__half2*)(Ch + (size_t)r * ldc + cb)       = __floats2half2_rn(v0, v1);
                if (r + 8 < M) *(__half2*)(Ch + (size_t)(r + 8) * ldc + cb) = __floats2half2_rn(v2, v3);
            }
        }
    }
}

// ---------------- kernels ------------------------------------------------------

__global__ void init_kernel(const float* __restrict__ inputs) {
    int idx = blockIdx.x * blockDim.x + threadIdx.x;
    if (idx < BN * H_) { g_hidden[idx] = 0.f; g_hidden_h[idx] = __float2half(0.f); }
    if (idx < BN * IN_) {
        int row = idx / IN_, c = idx % IN_;
        int b = row / N_, n = row % N_;
        g_ins[idx] = inputs[(((size_t)b * T_ + 0) * N_ + n) * IN_ + c];
    }
}

__global__ __launch_bounds__(128)
void urus_tc(int dummy) {
    int z = blockIdx.z;
    tc16_tile(g_hidden_h, H_, g_w1h + (size_t)z * HH, H_, nullptr,
              nullptr, g_Uh + (size_t)z * BN * H_, H_,
              BN, blockIdx.x * 64, blockIdx.y * 128, 0);
}

// ---- M1h: tanh(Ur[recv]+Us[send]+b1) fp16x2 ----------------------------------
__global__ __launch_bounds__(256)
void m1h_kernel() {
    const int tid = threadIdx.x;
    const int warp = tid >> 5, lane = tid & 31;
    const int row = blockIdx.x * 8 + warp;
    const int z = blockIdx.y;
    int b = row / E_;
    int e = row - b * E_;
    int send = e / 49, rr2 = e - send * 49;
    int recv = rr2 + (rr2 >= send);

    const __half* Ur = g_Uh + ((size_t)(2 * z) * BN + b * N_ + recv) * H_ + lane * 8;
    const __half* Us = g_Uh + ((size_t)(2 * z + 1) * BN + b * N_ + send) * H_ + lane * 8;
    const __half* B1 = g_b1h + (size_t)z * H_ + lane * 8;

    uint4 u = *(const uint4*)Ur;
    uint4 s = *(const uint4*)Us;
    uint4 bb = *(const uint4*)B1;
    uint4 o;
    o.x = tanh2(hadd2u(hadd2u(u.x, s.x), bb.x));
    o.y = tanh2(hadd2u(hadd2u(u.y, s.y), bb.y));
    o.z = tanh2(hadd2u(hadd2u(u.z, s.z), bb.z));
    o.w = tanh2(hadd2u(hadd2u(u.w, s.w), bb.w));
    *(uint4*)(g_M1h + ((size_t)z * BE + row) * H_ + lane * 8) = o;
}

// ======== edge-message GEMM =====================================================
__global__ __launch_bounds__(128, 4)
void msgs_f16_kernel(const float* __restrict__ msg_b2,
                     const float* __restrict__ edges, int t)
{
    __shared__ unsigned As[3][64][12];
    __shared__ unsigned Ws[3][128][12];
    __shared__ float relw[64];
    __shared__ float b2s[128];

    const int tid = threadIdx.x;
    const int lane = tid & 31, wid = tid >> 5;
    const int gid = lane >> 2, tig = lane & 3;
    const int wm0 = (wid >> 1) * 32, wn0 = (wid & 1) * 64;
    const int row0 = blockIdx.x * 64, col0 = blockIdx.y * 128;
    const int z = blockIdx.z, type = z + 1;

    if (tid < 64) {
        int r = row0 + tid;
        int valid = (r < BE);
        if (!valid) r = BE - 1;
        int b = r / E_;
        int e = r - b * E_;
        relw[tid] = valid
            ? edges[(((size_t)b * T_ + t) * E_ + e) * K_ + type] * (1.f / 3.f)
            : 0.f;
    }
    b2s[tid] = msg_b2[(size_t)type * H_ + col0 + tid];

    const int ar = tid >> 1, ap = tid & 1;
    int arow = row0 + ar; if (arow >= BE) arow = BE - 1;
    const __half* Apt = g_M1h + ((size_t)z * BE + arow) * H_ + ap * 8;
    const __half* Wpt = g_w2h + ((size_t)z * H_ + (col0 + tid)) * H_;

    const unsigned asA = su32(&As[0][0][0]);
    const unsigned asW = su32(&Ws[0][0][0]);
    const unsigned aoff0 = A_LOFF(lane, wm0);
    const unsigned aoff1 = A_LOFF(lane, wm0 + 16);
    const unsigned woff  = W_LOFF(lane, wn0);

#pragma unroll
    for (int p = 0; p < 2; p++) {
        cp16(su32(&As[p][ar][ap * 4]), Apt + p * 16);
        cp16(su32(&Ws[p][tid][0]), Wpt + p * 16);
        cp16(su32(&Ws[p][tid][4]), Wpt + p * 16 + 8);
        cp_commit();
    }

    float acc[2][8][4];
#pragma unroll
    for (int mi = 0; mi < 2; mi++)
#pragma unroll
        for (int ni = 0; ni < 8; ni++)
#pragma unroll
            for (int j = 0; j < 4; j++) acc[mi][ni][j] = 0.f;

#pragma unroll 1
    for (int c = 0; c < 16; c++) {
        if (c + 1 < 16) cp_wait1(); else cp_wait0();
        __syncthreads();
        int cn = c + 2;
        if (cn < 16) {
            int bf = cn % 3;
            cp16(su32(&As[bf][ar][ap * 4]), Apt + cn * 16);
            cp16(su32(&Ws[bf][tid][0]), Wpt + cn * 16);
            cp16(su32(&Ws[bf][tid][4]), Wpt + cn * 16 + 8);
            cp_commit();
        }
        const int b = c % 3;
        const unsigned abase = asA + (unsigned)b * 3072;
        const unsigned wbase = asW + (unsigned)b * 6144 + woff;
        unsigned a0[4], a1[4];
        ldsm4(a0[0], a0[1], a0[2], a0[3], abase + aoff0);
        ldsm4(a1[0], a1[1], a1[2], a1[3], abase + aoff1);
#pragma unroll
        for (int j = 0; j < 4; j++) {
            unsigned b00, b01, b10, b11;
            ldsm4(b00, b01, b10, b11, wbase + (unsigned)j * 768);
            mma16(acc[0][2 * j],     a0, b00, b01);
            mma16(acc[1][2 * j],     a1, b00, b01);
            mma16(acc[0][2 * j + 1], a0, b10, b11);
            mma16(acc[1][2 * j + 1], a1, b10, b11);
        }
    }

    __half* Cz = g_msgs3h + (size_t)z * BE * H_;
#pragma unroll
    for (int mi = 0; mi < 2; mi++) {
        int r = row0 + wm0 + mi * 16 + gid;
        __half2 rl0 = __float2half2_rn(relw[wm0 + mi * 16 + gid]);
        __half2 rl1 = __float2half2_rn(relw[wm0 + mi * 16 + gid + 8]);
#pragma unroll
        for (int ni = 0; ni < 8; ni++) {
            int cb = col0 + wn0 + ni * 8 + tig * 2;
            float bb0 = b2s[wn0 + ni * 8 + tig * 2];
            float bb1 = b2s[wn0 + ni * 8 + tig * 2 + 1];
            if (r < BE) {
                unsigned tr = tanh2(h2pack(acc[mi][ni][0] + bb0, acc[mi][ni][1] + bb1));
                *(__half2*)(Cz + (size_t)r * H_ + cb) =
                    __hmul2(*reinterpret_cast<__half2*>(&tr), rl0);
            }
            if (r + 8 < BE) {
                unsigned tr = tanh2(h2pack(acc[mi][ni][2] + bb0, acc[mi][ni][3] + bb1));
                *(__half2*)(Cz + (size_t)(r + 8) * H_ + cb) =
                    __hmul2(*reinterpret_cast<__half2*>(&tr), rl1);
            }
        }
    }
}

// agg: sum 3 fp16 type-buffers over 49 senders -> fp16
__global__ __launch_bounds__(256)
void agg_kernel() {
    __shared__ float part[3][256];
    const int tid = threadIdx.x;
    const int sg = tid >> 6;
    const int hq = tid & 63;
    const int row = blockIdx.x;
    const int b = row / N_, r = row - b * N_;
    float4 s = make_float4(0.f, 0.f, 0.f, 0.f);
#pragma unroll
    for (int z = 0; z < 3; z++) {
        const __half* base = g_msgs3h + ((size_t)z * BE + (size_t)b * E_) * H_ + hq * 4;
        for (int send = sg; send < N_; send += 4) {
            if (send == r) continue;
            int e = send * 49 + r - (r > send);
            uint2 raw = *(const uint2*)(base + (size_t)e * H_);
            float2 f01 = __half22float2(*reinterpret_cast<__half2*>(&raw.x));
            float2 f23 = __half22float2(*reinterpret_cast<__half2*>(&raw.y));
            s.x += f01.x; s.y += f01.y; s.z += f23.x; s.w += f23.y;
        }
    }
    if (sg > 0) *(float4*)&part[sg - 1][hq * 4] = s;
    __syncthreads();
    if (sg == 0) {
        const float4 p0 = *(const float4*)&part[0][hq * 4];
        const float4 p1 = *(const float4*)&part[1][hq * 4];
        const float4 p2 = *(const float4*)&part[2][hq * 4];
        const float inv = 1.f / 49.f;
        float4 o;
        o.x = (s.x + p0.x + p1.x + p2.x) * inv;
        o.y = (s.y + p0.y + p1.y + p2.y) * inv;
        o.z = (s.z + p0.z + p1.z + p2.z) * inv;
        o.w = (s.w + p0.w + p1.w + p2.w) * inv;
        *(__half2*)(g_agg_h + (size_t)row * H_ + hq * 4)     = __floats2half2_rn(o.x, o.y);
        *(__half2*)(g_agg_h + (size_t)row * H_ + hq * 4 + 2) = __floats2half2_rn(o.z, o.w);
    }
}

__global__ __launch_bounds__(128)
void gru_tc(int dummy) {
    int z = blockIdx.z;
    tc16_tile(g_agg_h, H_, g_whh3 + (size_t)z * HH, H_, nullptr,
              g_gru + (size_t)z * BN * H_, nullptr, H_,
              BN, blockIdx.x * 64, blockIdx.y * 128, 0);
}

__global__ void gruew_kernel(const float* __restrict__ w_ir, const float* __restrict__ b_ir,
                             const float* __restrict__ w_ii, const float* __restrict__ b_ii,
                             const float* __restrict__ w_in, const float* __restrict__ b_in) {
    int idx = blockIdx.x * blockDim.x + threadIdx.x;
    if (idx >= BN * H_) return;
    int row = idx / H_, h = idx - row * H_;
    float xr = b_ir[h], xi = b_ii[h], xn = b_in[h];
#pragma unroll
    for (int f = 0; f < IN_; f++) {
        float iv = g_ins[row * IN_ + f];
        xr += iv * w_ir[h * IN_ + f];
        xi += iv * w_ii[h * IN_ + f];
        xn += iv * w_in[h * IN_ + f];
    }
    float ar = g_gru[idx];
    float ai = g_gru[BN * H_ + idx];
    float ah = g_gru[2 * BN * H_ + idx];
    float r  = sigmoid_fast(xr + ar);
    float ig = sigmoid_fast(xi + ai);
    float nn = tanh_fast(xn + r * ah);
    float hnew = (1.f - ig) * nn + ig * g_hidden[idx];
    g_hidden[idx] = hnew;
    g_hidden_h[idx] = __float2half(hnew);
}

__global__ __launch_bounds__(128)
void p1_tc(const float* __restrict__ b_o1) {
    tc16_tile(g_hidden_h, H_, g_wo1h, H_, b_o1, nullptr, g_p1h, H_,
              BN, blockIdx.x * 64, blockIdx.y * 128, 1);
}
__global__ __launch_bounds__(128)
void p2_tc(const float* __restrict__ b_o2) {
    tc16_tile(g_p1h, H_, g_wo2h, H_, b_o2, g_p2, nullptr, H_,
              BN, blockIdx.x * 64, blockIdx.y * 128, 1);
}

__global__ void f3_kernel(const float* __restrict__ w_o3,
                          const float* __restrict__ b_o3,
                          float* __restrict__ out, int t) {
    int row = blockIdx.x;
    int w = threadIdx.x >> 5;
    int lane = threadIdx.x & 31;
    const float* pr = g_p2 + (size_t)row * H_;
    const float* wr = w_o3 + (size_t)w * H_;
    float s = 0.f;
    for (int j = lane; j < H_; j += 32) s += pr[j] * wr[j];
#pragma unroll
    for (int off = 16; off; off >>= 1) s += __shfl_down_sync(0xffffffffu, s, off);
    if (lane == 0) {
        int b = row / N_, n = row % N_;
        float v = g_ins[row * IN_ + w] + b_o3[w] + s;
        out[(((size_t)b * T_ + t) * N_ + n) * IN_ + w] = v;
        g_ins[row * IN_ + w] = v;
    }
}

// ---------------- launch ---------------------------------------------------------
extern "C" void kernel_launch(void* const* d_in, const int* in_sizes, int n_in,
                              void* d_out, int out_size) {
    const float* inputs = (const float*)d_in[0];
    const float* edges  = (const float*)d_in[1];
    const float* msg_w1 = (const float*)d_in[2];
    const float* msg_b1 = (const float*)d_in[3];
    const float* msg_w2 = (const float*)d_in[4];
    const float* msg_b2 = (const float*)d_in[5];
    const float* w_hr = (const float*)d_in[6];
    const float* w_hi = (const float*)d_in[7];
    const float* w_hh = (const float*)d_in[8];
    const float* w_ir = (const float*)d_in[9];
    const float* b_ir = (const float*)d_in[10];
    const float* w_ii = (const float*)d_in[11];
    const float* b_ii = (const float*)d_in[12];
    const float* w_in_ = (const float*)d_in[13];
    const float* b_in_ = (const float*)d_in[14];
    const float* w_o1 = (const float*)d_in[15];
    const float* b_o1 = (const float*)d_in[16];
    const float* w_o2 = (const float*)d_in[17];
    const float* b_o2 = (const float*)d_in[18];
    const float* w_o3 = (const float*)d_in[19];
    const float* b_o3 = (const float*)d_in[20];
    float* out = (float*)d_out;

    // second stream + fork/join events, created once OUTSIDE any capture
    static cudaStream_t s2 = nullptr;
    static cudaEvent_t evF = nullptr, evJ = nullptr;
    if (s2 == nullptr) {
        cudaStreamCreateWithFlags(&s2, cudaStreamNonBlocking);
        cudaEventCreateWithFlags(&evF, cudaEventDisableTiming);
        cudaEventCreateWithFlags(&evJ, cudaEventDisableTiming);
    }

    cvt_weights<<<(6 * HH + 255) / 256, 256>>>(msg_w1, msg_w2, w_hr, w_hi, w_hh,
                                               w_o1, w_o2, msg_b1);
    init_kernel<<<(BN * H_ + 255) / 256, 256>>>(inputs);

    const int rowt = (BE + 63) / 64;  // 307
    for (int t = 0; t < T_; t++) {
        if (t > 0) {
            // fork: output-MLP chain for step t-1 runs on s2, concurrent with
            // the message-passing chain for step t (both only READ g_hidden*).
            cudaEventRecord(evF, 0);
            cudaStreamWaitEvent(s2, evF, 0);
            p1_tc<<<dim3(7, 2), 128, 0, s2>>>(b_o1);
            p2_tc<<<dim3(7, 2), 128, 0, s2>>>(b_o2);
            f3_kernel<<<BN, 192, 0, s2>>>(w_o3, b_o3, out, t - 1);
            cudaEventRecord(evJ, s2);
        }
        urus_tc<<<dim3(7, 2, 6), 128>>>(0);
        m1h_kernel<<<dim3(BE / 8, 3), 256>>>();
        msgs_f16_kernel<<<dim3(rowt, 2, 3), 128>>>(msg_b2, edges, t);
        agg_kernel<<<BN, 256>>>();
        gru_tc<<<dim3(7, 2, 3), 128>>>(0);
        if (t > 0) cudaStreamWaitEvent(0, evJ, 0);   // join: need g_ins from f3(t-1)
        gruew_kernel<<<(BN * H_ + 255) / 256, 256>>>(w_ir, b_ir, w_ii, b_ii, w_in_, b_in_);
    }
    // final step's output MLP
    p1_tc<<<dim3(7, 2), 128>>>(b_o1);
    p2_tc<<<dim3(7, 2), 128>>>(b_o2);
    f3_kernel<<<BN, 192>>>(w_o3, b_o3, out, T_ - 1);
}